// round 10
// baseline (speedup 1.0000x reference)
#include <cuda_runtime.h>

// PARCOR (reflection) coefficients -> LPC coefficients (Levinson step-up).
// Input  k : [N, 25] float32  (N = 2097152)
// Output a : [N, 25] float32
//
// Per row:
//   a = k
//   for m in 2..24:
//     a[1:m] = a[1:m] + k[m] * a[1:m][::-1]
// Note k[m] == a[m] at the time step m executes (index m only modified by
// later steps), so the recursion is fully in-place on a 25-register array.

#define ORDER_P1 25           // LPC_ORDER + 1
#define ROWS_PER_BLOCK 128
#define THREADS 128
#define TILE_ELEMS (ROWS_PER_BLOCK * ORDER_P1)   // 3200 floats = 12.5 KB

__global__ __launch_bounds__(THREADS)
void parcor_to_lpc_kernel(const float* __restrict__ k,
                          float* __restrict__ out,
                          int nrows)
{
    __shared__ float smem[TILE_ELEMS];

    const int t = threadIdx.x;
    const long long block_row0 = (long long)blockIdx.x * ROWS_PER_BLOCK;
    const long long base = block_row0 * ORDER_P1;
    const long long nelem = (long long)nrows * ORDER_P1;

    // ---- coalesced stage-in: 128 rows x 25 floats, linear copy ----
    #pragma unroll
    for (int i = 0; i < TILE_ELEMS; i += THREADS) {
        long long g = base + i + t;
        if (g < nelem) smem[i + t] = k[g];
    }
    __syncthreads();

    const long long row = block_row0 + t;
    float a[ORDER_P1];

    if (row < nrows) {
        // stride-25 smem reads: gcd(25,32)=1 -> conflict-free across a warp
        #pragma unroll
        for (int j = 0; j < ORDER_P1; j++) a[j] = smem[t * ORDER_P1 + j];

        // ---- Levinson step-up, fully unrolled in registers ----
        #pragma unroll
        for (int m = 2; m <= 24; m++) {
            const float km = a[m];      // == original k[m] (untouched so far)
            #pragma unroll
            for (int j = 1; 2 * j < m; j++) {
                const float x = a[j];
                const float y = a[m - j];
                a[j]     = fmaf(km, y, x);
                a[m - j] = fmaf(km, x, y);
            }
            if ((m & 1) == 0) {
                const int j = m >> 1;   // midpoint: a[j] += km * a[j]
                a[j] = fmaf(km, a[j], a[j]);
            }
        }
    }

    __syncthreads();   // smem reuse for stage-out

    if (row < nrows) {
        #pragma unroll
        for (int j = 0; j < ORDER_P1; j++) smem[t * ORDER_P1 + j] = a[j];
    }
    __syncthreads();

    // ---- coalesced stage-out ----
    #pragma unroll
    for (int i = 0; i < TILE_ELEMS; i += THREADS) {
        long long g = base + i + t;
        if (g < nelem) out[g] = smem[i + t];
    }
}

extern "C" void kernel_launch(void* const* d_in, const int* in_sizes, int n_in,
                              void* d_out, int out_size)
{
    const float* k = (const float*)d_in[0];
    float* out = (float*)d_out;

    const int nrows = in_sizes[0] / ORDER_P1;   // 2097152
    const int grid = (nrows + ROWS_PER_BLOCK - 1) / ROWS_PER_BLOCK;

    parcor_to_lpc_kernel<<<grid, THREADS>>>(k, out, nrows);
}

// round 11
// speedup vs baseline: 1.7312x; 1.7312x over previous
#include <cuda_runtime.h>
#include <cstdint>

// PARCOR (reflection) -> LPC coefficients (Levinson step-up), k: [2097152, 25] f32.
//
// Per row: a = k; for m in 2..24: a[1:m] += k[m] * a[1:m][::-1]
// k[m] == a[m] when step m runs (index m only touched by later steps), so the
// recursion is fully in-place on a 25-register array.
//
// Memory strategy: one 12.8 KB tile (128 rows) per block, moved with
// cp.async.bulk (TMA) in both directions. No per-thread LDG/STG, no staging
// registers -> low reg pressure, high resident-block count, and the full tile
// is in flight from a single instruction (latency-hiding without relying on
// ptxas load batching).

#define ORDER_P1 25
#define ROWS 128
#define THREADS 128
#define TILE_FLOATS (ROWS * ORDER_P1)       // 3200
#define TILE_BYTES  (TILE_FLOATS * 4)       // 12800, 16B-multiple & aligned

__global__ __launch_bounds__(THREADS)
void parcor_to_lpc_kernel(const float* __restrict__ kin,
                          float* __restrict__ out)
{
    __shared__ alignas(128) float tile[TILE_FLOATS];
    __shared__ alignas(8) unsigned long long mbar;

    const int t = threadIdx.x;
    const size_t base = (size_t)blockIdx.x * TILE_FLOATS;

    const uint32_t s_tile = (uint32_t)__cvta_generic_to_shared(tile);
    const uint32_t s_mbar = (uint32_t)__cvta_generic_to_shared(&mbar);

    // ---- init mbarrier, make it visible to the async proxy ----
    if (t == 0) {
        asm volatile("mbarrier.init.shared.b64 [%0], 1;" :: "r"(s_mbar) : "memory");
        asm volatile("fence.proxy.async.shared::cta;" ::: "memory");
    }
    __syncthreads();

    // ---- bulk copy-in: whole tile, one TMA op, tx-count completion ----
    if (t == 0) {
        asm volatile("mbarrier.arrive.expect_tx.shared.b64 _, [%0], %1;"
                     :: "r"(s_mbar), "r"((uint32_t)TILE_BYTES) : "memory");
        asm volatile(
            "cp.async.bulk.shared::cta.global.mbarrier::complete_tx::bytes "
            "[%0], [%1], %2, [%3];"
            :: "r"(s_tile), "l"(kin + base), "r"((uint32_t)TILE_BYTES), "r"(s_mbar)
            : "memory");
    }

    // ---- all threads wait (parity 0, acquire) ----
    {
        uint32_t done;
        asm volatile(
            "{\n\t.reg .pred p;\n\t"
            "mbarrier.try_wait.parity.acquire.cta.shared::cta.b64 p, [%1], 0;\n\t"
            "selp.b32 %0, 1, 0, p;\n\t}"
            : "=r"(done) : "r"(s_mbar) : "memory");
        while (!done) {
            asm volatile(
                "{\n\t.reg .pred p;\n\t"
                "mbarrier.try_wait.parity.acquire.cta.shared::cta.b64 p, [%1], 0, 0x989680;\n\t"
                "selp.b32 %0, 1, 0, p;\n\t}"
                : "=r"(done) : "r"(s_mbar) : "memory");
        }
    }

    // ---- load own row (stride-25 smem: gcd(25,32)=1 -> conflict-free) ----
    float a[ORDER_P1];
    #pragma unroll
    for (int j = 0; j < ORDER_P1; j++) a[j] = tile[t * ORDER_P1 + j];

    // ---- Levinson step-up, fully unrolled in registers ----
    #pragma unroll
    for (int m = 2; m <= 24; m++) {
        const float km = a[m];          // == original k[m]
        #pragma unroll
        for (int j = 1; 2 * j < m; j++) {
            const float x = a[j];
            const float y = a[m - j];
            a[j]     = fmaf(km, y, x);
            a[m - j] = fmaf(km, x, y);
        }
        if ((m & 1) == 0) {
            const int j = m >> 1;
            a[j] = fmaf(km, a[j], a[j]);   // midpoint: a[j] *= (1 + km)
        }
    }

    // ---- write own row back in place (WAR is intra-thread only) ----
    #pragma unroll
    for (int j = 0; j < ORDER_P1; j++) tile[t * ORDER_P1 + j] = a[j];

    // generic-proxy STS must be visible to the async-proxy bulk store
    asm volatile("fence.proxy.async.shared::cta;" ::: "memory");
    __syncthreads();

    // ---- bulk copy-out ----
    if (t == 0) {
        asm volatile(
            "cp.async.bulk.global.shared::cta.bulk_group [%0], [%1], %2;"
            :: "l"(out + base), "r"(s_tile), "r"((uint32_t)TILE_BYTES)
            : "memory");
        asm volatile("cp.async.bulk.commit_group;" ::: "memory");
        asm volatile("cp.async.bulk.wait_group 0;" ::: "memory");
    }
}

extern "C" void kernel_launch(void* const* d_in, const int* in_sizes, int n_in,
                              void* d_out, int out_size)
{
    const float* k = (const float*)d_in[0];
    float* out = (float*)d_out;

    const int nrows = in_sizes[0] / ORDER_P1;       // 2097152, divisible by 128
    const int grid = nrows / ROWS;                  // 16384

    parcor_to_lpc_kernel<<<grid, THREADS>>>(k, out);
}

// round 12
// speedup vs baseline: 1.7379x; 1.0039x over previous
#include <cuda_runtime.h>
#include <cstdint>

// PARCOR (reflection) -> LPC coefficients (Levinson step-up), k: [2097152, 25] f32.
//
// Per row: a = k; for m in 2..24: a[1:m] += k[m] * a[1:m][::-1]
// k[m] == a[m] when step m runs (index m only touched by later steps), so the
// recursion is fully in-place on a 25-register array.
//
// Memory strategy: one 25.6 KB tile (256 rows) per block, moved with
// cp.async.bulk (TMA) in both directions. 256 threads, 32 regs -> 8 blocks/SM
// (64 warps, full occupancy) with 205 KB/SM of tile traffic in flight across
// staggered block phases. No per-thread LDG/STG.

#define ORDER_P1 25
#define ROWS 256
#define THREADS 256
#define TILE_FLOATS (ROWS * ORDER_P1)       // 6400
#define TILE_BYTES  (TILE_FLOATS * 4)       // 25600, 16B-multiple & aligned

__global__ __launch_bounds__(THREADS)
void parcor_to_lpc_kernel(const float* __restrict__ kin,
                          float* __restrict__ out)
{
    __shared__ alignas(128) float tile[TILE_FLOATS];
    __shared__ alignas(8) unsigned long long mbar;

    const int t = threadIdx.x;
    const size_t base = (size_t)blockIdx.x * TILE_FLOATS;

    const uint32_t s_tile = (uint32_t)__cvta_generic_to_shared(tile);
    const uint32_t s_mbar = (uint32_t)__cvta_generic_to_shared(&mbar);

    // ---- init mbarrier, make it visible to the async proxy ----
    if (t == 0) {
        asm volatile("mbarrier.init.shared.b64 [%0], 1;" :: "r"(s_mbar) : "memory");
        asm volatile("fence.proxy.async.shared::cta;" ::: "memory");
    }
    __syncthreads();

    // ---- bulk copy-in: whole tile, one TMA op, tx-count completion ----
    if (t == 0) {
        asm volatile("mbarrier.arrive.expect_tx.shared.b64 _, [%0], %1;"
                     :: "r"(s_mbar), "r"((uint32_t)TILE_BYTES) : "memory");
        asm volatile(
            "cp.async.bulk.shared::cta.global.mbarrier::complete_tx::bytes "
            "[%0], [%1], %2, [%3];"
            :: "r"(s_tile), "l"(kin + base), "r"((uint32_t)TILE_BYTES), "r"(s_mbar)
            : "memory");
    }

    // ---- all threads wait (parity 0, acquire) ----
    {
        uint32_t done;
        asm volatile(
            "{\n\t.reg .pred p;\n\t"
            "mbarrier.try_wait.parity.acquire.cta.shared::cta.b64 p, [%1], 0;\n\t"
            "selp.b32 %0, 1, 0, p;\n\t}"
            : "=r"(done) : "r"(s_mbar) : "memory");
        while (!done) {
            asm volatile(
                "{\n\t.reg .pred p;\n\t"
                "mbarrier.try_wait.parity.acquire.cta.shared::cta.b64 p, [%1], 0, 0x989680;\n\t"
                "selp.b32 %0, 1, 0, p;\n\t}"
                : "=r"(done) : "r"(s_mbar) : "memory");
        }
    }

    // ---- load own row (stride-25 smem: gcd(25,32)=1 -> conflict-free) ----
    float a[ORDER_P1];
    #pragma unroll
    for (int j = 0; j < ORDER_P1; j++) a[j] = tile[t * ORDER_P1 + j];

    // ---- Levinson step-up, fully unrolled in registers ----
    #pragma unroll
    for (int m = 2; m <= 24; m++) {
        const float km = a[m];          // == original k[m]
        #pragma unroll
        for (int j = 1; 2 * j < m; j++) {
            const float x = a[j];
            const float y = a[m - j];
            a[j]     = fmaf(km, y, x);
            a[m - j] = fmaf(km, x, y);
        }
        if ((m & 1) == 0) {
            const int j = m >> 1;
            a[j] = fmaf(km, a[j], a[j]);   // midpoint: a[j] *= (1 + km)
        }
    }

    // ---- write own row back in place (WAR is intra-thread only) ----
    #pragma unroll
    for (int j = 0; j < ORDER_P1; j++) tile[t * ORDER_P1 + j] = a[j];

    // generic-proxy STS must be visible to the async-proxy bulk store
    asm volatile("fence.proxy.async.shared::cta;" ::: "memory");
    __syncthreads();

    // ---- bulk copy-out ----
    if (t == 0) {
        asm volatile(
            "cp.async.bulk.global.shared::cta.bulk_group [%0], [%1], %2;"
            :: "l"(out + base), "r"(s_tile), "r"((uint32_t)TILE_BYTES)
            : "memory");
        asm volatile("cp.async.bulk.commit_group;" ::: "memory");
        asm volatile("cp.async.bulk.wait_group 0;" ::: "memory");
    }
}

extern "C" void kernel_launch(void* const* d_in, const int* in_sizes, int n_in,
                              void* d_out, int out_size)
{
    const float* k = (const float*)d_in[0];
    float* out = (float*)d_out;

    const int nrows = in_sizes[0] / ORDER_P1;       // 2097152, divisible by 256
    const int grid = nrows / ROWS;                  // 8192

    parcor_to_lpc_kernel<<<grid, THREADS>>>(k, out);
}